// round 9
// baseline (speedup 1.0000x reference)
#include <cuda_runtime.h>
#include <cstdint>

// Output layout (floats), tuple order (c_all, y_all, GBT_A, GBT_B):
//   c_all : [1024,256]      offset 0        size 262144
//   y_all : [1024]          offset 262144   size 1024
//   GBT_A : [1024,256,256]  offset 263168   size 67108864
//   GBT_B : [1024,256]      offset 67372032 size 262144
#define OC 0
#define OY 262144
#define OA 263168
#define OB 67372032

#define RING    88
#define RSTRIDE 256                       // floats per ring row; 1KB => 16B-aligned rows
#define RINGB   (RING * RSTRIDE * 4)      // 90112
#define SMEMB   (8192 + RINGB + 16)       // tab | ring | progress

static __device__ __forceinline__ float frcp(float x) {
    float y; asm("rcp.approx.ftz.f32 %0,%1;" : "=f"(y) : "f"(x)); return y;
}

__global__ __launch_bounds__(256) void hippo_fused(
    const float* __restrict__ f,
    const float* __restrict__ init_state,
    const float* __restrict__ Bv,
    float* __restrict__ out)
{
    extern __shared__ char dsm[];
    const int bid = blockIdx.x;
    const int tid = threadIdx.x;

    if (bid == 0) {
        // ======= scan: c_all + y_all. ONE compute warp, barrier-free =======
        // c_k = P1_k^{-1}(2 c_{k-1} + s_k f_k B) - c_{k-1}; O(N) solve:
        //   x_i = (u_i - h r_i S_i)/d_i ;  S_{i+1} = S_i + r_i x_i
        // lane l owns i in [8l, 8l+8); B=2 timesteps per iter; k = 2(T-l).
        float2* tab  = (float2*)dsm;                 // (s_k*f_k, h_k)
        float*  ring = (float*)(dsm + 8192);         // [RING][RSTRIDE]
        int*    prog = (int*)(dsm + 8192 + RINGB);
        const uint32_t paddr = (uint32_t)__cvta_generic_to_shared(prog);

        for (int kq = tid; kq < 1024; kq += 256) {
            float s = frcp((float)(kq + 1));
            tab[kq] = make_float2(s * f[kq], 0.5f * s);
        }
        if (tid == 0) *prog = 0;
        __syncthreads();                             // one-time only

        const int w = tid >> 5, lane = tid & 31;
        if (w == 0) {
            // -------- compute warp (SMSP0) --------
            float r8[8], c8[8], ip[8];
            {
                float4 a = *(const float4*)(Bv + 8 * lane);
                float4 b = *(const float4*)(Bv + 8 * lane + 4);
                r8[0]=a.x; r8[1]=a.y; r8[2]=a.z; r8[3]=a.w;
                r8[4]=b.x; r8[5]=b.y; r8[6]=b.z; r8[7]=b.w;
                float4 c0 = *(const float4*)(init_state + 8 * lane);
                float4 c1 = *(const float4*)(init_state + 8 * lane + 4);
                c8[0]=c0.x; c8[1]=c0.y; c8[2]=c0.z; c8[3]=c0.w;
                c8[4]=c1.x; c8[5]=c1.y; c8[6]=c1.z; c8[7]=c1.w;
            }
            #pragma unroll
            for (int m = 0; m < 8; m++) ip[m] = (float)(8 * lane + m + 1);

            float Sin0 = 0.f, yin0 = 0.f, Sin1 = 0.f, yin1 = 0.f;

            for (int T = 0; T < 543; T++) {
                const int  kd    = T - lane;
                const bool valid = ((unsigned)kd < 512u);
                const int  k0    = valid ? (kd << 1) : 0;

                float2 t0 = tab[k0];
                float2 t1 = tab[k0 + 1];
                const float sf0 = t0.x, h0 = t0.y;
                const float sf1 = t1.x, h1 = t1.y;

                float iv0[8], iv1[8];
                #pragma unroll
                for (int m = 0; m < 8; m++) {
                    iv0[m] = frcp(fmaf(h0, ip[m], 1.0f));
                    iv1[m] = frcp(fmaf(h1, ip[m], 1.0f));
                }

                float S0 = Sin0, y0 = yin0, S1 = Sin1, y1 = yin1;
                float o0[8], o1[8];
                #pragma unroll
                for (int m = 0; m < 8; m++) {
                    float r = r8[m], c = c8[m];
                    // timestep k0
                    float u0  = fmaf(sf0, r, c + c);
                    float x0  = fmaf(-h0 * r, S0, u0) * iv0[m];
                    S0        = fmaf(r, x0, S0);
                    float cn0 = x0 - c;
                    y0 += cn0;
                    // timestep k0+1 (uses cn0)
                    float u1  = fmaf(sf1, r, cn0 + cn0);
                    float x1  = fmaf(-h1 * r, S1, u1) * iv1[m];
                    S1        = fmaf(r, x1, S1);
                    float cn1 = x1 - cn0;
                    y1 += cn1;
                    o0[m] = cn0; o1[m] = cn1;
                    if (valid) c8[m] = cn1;
                }

                if (valid) {
                    float* p0 = ring + (unsigned)(k0 % RING) * RSTRIDE + 8 * lane;
                    float* p1 = ring + (unsigned)((k0 + 1) % RING) * RSTRIDE + 8 * lane;
                    *(float4*)p0       = make_float4(o0[0], o0[1], o0[2], o0[3]);
                    *(float4*)(p0 + 4) = make_float4(o0[4], o0[5], o0[6], o0[7]);
                    *(float4*)p1       = make_float4(o1[0], o1[1], o1[2], o1[3]);
                    *(float4*)(p1 + 4) = make_float4(o1[4], o1[5], o1[6], o1[7]);
                    if (lane == 31) { out[OY + k0] = y0; out[OY + k0 + 1] = y1; }
                }

                float nS0 = __shfl_up_sync(0xffffffffu, S0, 1);
                float ny0 = __shfl_up_sync(0xffffffffu, y0, 1);
                float nS1 = __shfl_up_sync(0xffffffffu, S1, 1);
                float ny1 = __shfl_up_sync(0xffffffffu, y1, 1);
                if (lane == 0) { nS0 = 0.f; ny0 = 0.f; nS1 = 0.f; ny1 = 0.f; }
                Sin0 = nS0; yin0 = ny0; Sin1 = nS1; yin1 = ny1;

                // publish completed rows (release) every 4 iters
                if (((T & 3) == 3) && T >= 31) {
                    __syncwarp();
                    if (lane == 0) {
                        int P = 2 * (T - 31) + 2;
                        asm volatile("st.release.cta.shared.b32 [%0], %1;"
                                     :: "r"(paddr), "r"(P) : "memory");
                    }
                }
            }
            __syncwarp();
            if (lane == 0) {
                int P = 1024;
                asm volatile("st.release.cta.shared.b32 [%0], %1;"
                             :: "r"(paddr), "r"(P) : "memory");
            }
        } else if (w == 1) {
            // -------- flush warp (SMSP1): ring -> c_all, coalesced --------
            int got = 0;
            for (int r = 0; r < 1024; r++) {
                while (got <= r) {
                    asm volatile("ld.acquire.cta.shared.b32 %0, [%1];"
                                 : "=r"(got) : "r"(paddr) : "memory");
                }
                const float* src = ring + (unsigned)(r % RING) * RSTRIDE;
                float4 a = *(const float4*)(src + 4 * lane);
                float4 b = *(const float4*)(src + 128 + 4 * lane);
                float* dst = out + OC + ((size_t)r << 8);
                *(float4*)(dst + 4 * lane)       = a;
                *(float4*)(dst + 128 + 4 * lane) = b;
            }
        }
        // warps 2..7: exit after tab fill
    } else if (bid <= 256) {
        // ========== GBT_A sweep: 4 timesteps per block (R2 form) ==========
        __shared__ float t_sh[4][256];
        const int grp = tid >> 6;
        const int g   = tid & 63;
        const int k   = ((bid - 1) << 2) + grp;
        const float s = frcp((float)(k + 1));
        const float h = 0.5f * s;

        #pragma unroll
        for (int m = 0; m < 4; m++) {
            int i = g + (m << 6);
            float tv = 0.0f;
            if (i >= 1) {
                float ri  = __ldg(Bv + i);
                float rim = __ldg(Bv + i - 1);
                float di  = fmaf(h, (float)(i + 1), 1.0f);
                tv = ri * (1.0f - h * (float)(i - 1)) * frcp(rim * di);
            }
            t_sh[grp][i] = tv;
        }
        __syncthreads();

        const int j0 = g << 2;
        float invd[5];
        #pragma unroll
        for (int m = 0; m < 5; m++)
            invd[m] = frcp(fmaf(h, (float)(j0 + m + 1), 1.0f));

        float diag[4], start[4], val[4];
        #pragma unroll
        for (int m = 0; m < 4; m++) {
            int j = j0 + m;
            diag[m] = (1.0f - h * (float)(j + 1)) * invd[m];
            float rj  = __ldg(Bv + j);
            float rj1 = (j + 1 < 256) ? __ldg(Bv + j + 1) : 0.0f;
            start[m] = -2.0f * h * rj1 * rj * invd[m] * invd[m + 1];
            val[m] = 0.0f;
        }

        float4* outp = (float4*)(out + OA + ((size_t)k << 16) + j0);
        for (int i = 0; i < 256; i++) {
            float tv = t_sh[grp][i];
            float4 v;
            #pragma unroll
            for (int m = 0; m < 4; m++) {
                int j = j0 + m;
                val[m] = (i == j + 1) ? start[m] : val[m] * tv;
                float vv = (i < j) ? 0.0f : ((i == j) ? diag[m] : val[m]);
                ((float*)&v)[m] = vv;
            }
            outp[(size_t)i << 6] = v;
        }
    } else {
        // ========== GBT_B: thread per timestep, float4-batched stores =====
        __shared__ float rsh[256];
        rsh[tid] = __ldg(Bv + tid);
        __syncthreads();
        const int k = ((bid - 257) << 8) + tid;
        const float s = frcp((float)(k + 1));
        const float h = 0.5f * s;
        float S = 0.0f;
        float4* outB = (float4*)(out + OB + ((size_t)k << 8));
        const float4* r4p = (const float4*)rsh;
        #pragma unroll 4
        for (int i4 = 0; i4 < 64; i4++) {
            float4 r4 = r4p[i4];
            float4 v;
            #pragma unroll
            for (int m = 0; m < 4; m++) {
                int i = (i4 << 2) + m;
                float r    = (&r4.x)[m];
                float invd = frcp(fmaf(h, (float)(i + 1), 1.0f));
                float x    = r * fmaf(-h, S, 1.0f) * invd;
                (&v.x)[m]  = s * x;
                S = fmaf(r, x, S);
            }
            outB[i4] = v;
        }
    }
}

extern "C" void kernel_launch(void* const* d_in, const int* in_sizes, int n_in,
                              void* d_out, int out_size) {
    const float* f          = (const float*)d_in[0];
    const float* init_state = (const float*)d_in[1];
    const float* Bv         = (const float*)d_in[3];
    cudaFuncSetAttribute(hippo_fused, cudaFuncAttributeMaxDynamicSharedMemorySize,
                         SMEMB);
    hippo_fused<<<261, 256, SMEMB>>>(f, init_state, Bv, (float*)d_out);
}

// round 11
// speedup vs baseline: 1.3317x; 1.3317x over previous
#include <cuda_runtime.h>
#include <cstdint>

// Output layout (floats), tuple order (c_all, y_all, GBT_A, GBT_B):
//   c_all : [1024,256]      offset 0        size 262144
//   y_all : [1024]          offset 262144   size 1024
//   GBT_A : [1024,256,256]  offset 263168   size 67108864
//   GBT_B : [1024,256]      offset 67372032 size 262144
#define OC 0
#define OY 262144
#define OA 263168
#define OB 67372032

#define RING    96                        // even; rows 1KB => 16B-aligned
#define RSTRIDE 256
#define RINGB   (RING * RSTRIDE * 4)      // 98304
#define SMEMB   (8192 + RINGB + 32)      // tab | ring | prog,fprog

static __device__ __forceinline__ float frcp(float x) {
    float y; asm("rcp.approx.ftz.f32 %0,%1;" : "=f"(y) : "f"(x)); return y;
}

__global__ __launch_bounds__(256) void hippo_fused(
    const float* __restrict__ f,
    const float* __restrict__ init_state,
    const float* __restrict__ Bv,
    float* __restrict__ out)
{
    extern __shared__ char dsm[];
    const int bid = blockIdx.x;
    const int tid = threadIdx.x;

    if (bid == 0) {
        // ======= scan: c_all + y_all. ONE compute warp, barrier-free =======
        // c_k = P1_k^{-1}(2 c_{k-1} + s_k f_k B) - c_{k-1}; O(N) solve:
        //   x_i = (u_i - h r_i S_i)/d_i ;  S_{i+1} = S_i + r_i x_i
        // lane l owns i in [8l,8l+8); 2 timesteps per iter; k0 = 2(T-l).
        float2* tab  = (float2*)dsm;                     // (s_k*f_k, h_k)
        float*  ring = (float*)(dsm + 8192);             // [RING][RSTRIDE]
        int*    prog = (int*)(dsm + 8192 + RINGB);       // [0]=rows published
        int*    fprg = prog + 1;                         // [1]=rows flushed
        const uint32_t paddr = (uint32_t)__cvta_generic_to_shared(prog);
        const uint32_t faddr = (uint32_t)__cvta_generic_to_shared(fprg);

        for (int kq = tid; kq < 1024; kq += 256) {
            float s = frcp((float)(kq + 1));
            tab[kq] = make_float2(s * f[kq], 0.5f * s);
        }
        if (tid == 0) { *prog = 0; *fprg = 0; }
        __syncthreads();                                 // one-time only

        const int w = tid >> 5, lane = tid & 31;
        if (w == 0) {
            // -------- compute warp (SMSP0), no barriers, no arrays beyond state ----
            float r8[8], c8[8];
            {
                float4 a = *(const float4*)(Bv + 8 * lane);
                float4 b = *(const float4*)(Bv + 8 * lane + 4);
                r8[0]=a.x; r8[1]=a.y; r8[2]=a.z; r8[3]=a.w;
                r8[4]=b.x; r8[5]=b.y; r8[6]=b.z; r8[7]=b.w;
                float4 c0 = *(const float4*)(init_state + 8 * lane);
                float4 c1 = *(const float4*)(init_state + 8 * lane + 4);
                c8[0]=c0.x; c8[1]=c0.y; c8[2]=c0.z; c8[3]=c0.w;
                c8[4]=c1.x; c8[5]=c1.y; c8[6]=c1.z; c8[7]=c1.w;
            }
            const float ip0 = (float)(8 * lane + 1);
            float Sin0 = 0.f, yin0 = 0.f, Sin1 = 0.f, yin1 = 0.f;
            int rrow = -2 * lane;                        // = 2(T-lane) mod RING once >= 0

            for (int T = 0; T < 543; T++) {
                const int  kd    = T - lane;
                const bool valid = ((unsigned)kd < 512u);
                const int  k0    = valid ? (kd << 1) : 0;

                float2 t0 = tab[k0];
                float2 t1 = tab[k0 + 1];
                const float sf0 = t0.x, h0 = t0.y;
                const float sf1 = t1.x, h1 = t1.y;

                float S0 = Sin0, y0 = yin0, S1 = Sin1, y1 = yin1;
                float* p0 = ring + rrow * RSTRIDE + 8 * lane;  // rrow even; row+1 adjacent

                #pragma unroll
                for (int m = 0; m < 8; m++) {
                    float r = r8[m], c = c8[m];
                    float ipm = ip0 + (float)m;
                    // timestep k0
                    float iv0 = frcp(fmaf(h0, ipm, 1.0f));
                    float u0  = fmaf(sf0, r, c + c);
                    float x0  = fmaf(-h0 * r, S0, u0) * iv0;
                    S0        = fmaf(r, x0, S0);
                    float cn0 = x0 - c;
                    y0 += cn0;
                    // timestep k0+1 (uses cn0)
                    float iv1 = frcp(fmaf(h1, ipm, 1.0f));
                    float u1  = fmaf(sf1, r, cn0 + cn0);
                    float x1  = fmaf(-h1 * r, S1, u1) * iv1;
                    S1        = fmaf(r, x1, S1);
                    float cn1 = x1 - cn0;
                    y1 += cn1;
                    if (valid) {                          // predicated STS.32 x2
                        c8[m] = cn1;
                        p0[m] = cn0;
                        p0[RSTRIDE + m] = cn1;
                    }
                }
                if (valid && lane == 31) { out[OY + k0] = y0; out[OY + k0 + 1] = y1; }

                float nS0 = __shfl_up_sync(0xffffffffu, S0, 1);
                float ny0 = __shfl_up_sync(0xffffffffu, y0, 1);
                float nS1 = __shfl_up_sync(0xffffffffu, S1, 1);
                float ny1 = __shfl_up_sync(0xffffffffu, y1, 1);
                if (lane == 0) { nS0 = 0.f; ny0 = 0.f; nS1 = 0.f; ny1 = 0.f; }
                Sin0 = nS0; yin0 = ny0; Sin1 = nS1; yin1 = ny1;

                rrow += 2; if (rrow >= RING) rrow -= RING;

                if (((T & 3) == 3) && T >= 31) {
                    __syncwarp();
                    if (lane == 0) {
                        int P = 2 * (T - 31) + 2;         // rows 0..P-1 complete
                        asm volatile("st.release.cta.shared.b32 [%0], %1;"
                                     :: "r"(paddr), "r"(P) : "memory");
                    }
                    // backpressure: rows written next 4 iters reach 2(T+4)+1;
                    // need row 2T+9-RING flushed => fprg >= 2T+10-RING
                    int need = 2 * T + 10 - RING;
                    if (need > 0) {
                        int fp;
                        do {
                            asm volatile("ld.acquire.cta.shared.b32 %0, [%1];"
                                         : "=r"(fp) : "r"(faddr) : "memory");
                        } while (fp < need);
                    }
                }
            }
            __syncwarp();
            if (lane == 0) {
                int P = 1024;
                asm volatile("st.release.cta.shared.b32 [%0], %1;"
                             :: "r"(paddr), "r"(P) : "memory");
            }
        } else if (w == 1) {
            // -------- flush warp (SMSP1): ring -> c_all, coalesced --------
            int got = 0, rrow = 0;
            for (int r = 0; r < 1024; r++) {
                while (got <= r) {
                    asm volatile("ld.acquire.cta.shared.b32 %0, [%1];"
                                 : "=r"(got) : "r"(paddr) : "memory");
                }
                const float* src = ring + rrow * RSTRIDE;
                float4 a = *(const float4*)(src + 4 * lane);
                float4 b = *(const float4*)(src + 128 + 4 * lane);
                float* dst = out + OC + ((size_t)r << 8);
                *(float4*)(dst + 4 * lane)       = a;      // STG consumes a,b =>
                *(float4*)(dst + 128 + 4 * lane) = b;      // LDS provably complete
                rrow++; if (rrow == RING) rrow = 0;
                if ((r & 3) == 3 && lane == 0) {
                    int fp = r + 1;                        // plain store, after STGs
                    asm volatile("st.relaxed.cta.shared.b32 [%0], %1;"
                                 :: "r"(faddr), "r"(fp) : "memory");
                }
            }
        }
        // warps 2..7: exit after tab fill
    } else if (bid <= 256) {
        // ========== GBT_A sweep: 4 timesteps per block ==========
        __shared__ float t_sh[4][256];
        const int grp = tid >> 6;
        const int g   = tid & 63;
        const int k   = ((bid - 1) << 2) + grp;
        const float s = frcp((float)(k + 1));
        const float h = 0.5f * s;

        #pragma unroll
        for (int m = 0; m < 4; m++) {
            int i = g + (m << 6);
            float tv = 0.0f;
            if (i >= 1) {
                float ri  = __ldg(Bv + i);
                float rim = __ldg(Bv + i - 1);
                float di  = fmaf(h, (float)(i + 1), 1.0f);
                tv = ri * (1.0f - h * (float)(i - 1)) * frcp(rim * di);
            }
            t_sh[grp][i] = tv;
        }
        __syncthreads();

        const int j0 = g << 2;
        float invd[5];
        #pragma unroll
        for (int m = 0; m < 5; m++)
            invd[m] = frcp(fmaf(h, (float)(j0 + m + 1), 1.0f));

        float diag[4], start[4], val[4];
        #pragma unroll
        for (int m = 0; m < 4; m++) {
            int j = j0 + m;
            diag[m] = (1.0f - h * (float)(j + 1)) * invd[m];
            float rj  = __ldg(Bv + j);
            float rj1 = (j + 1 < 256) ? __ldg(Bv + j + 1) : 0.0f;
            start[m] = -2.0f * h * rj1 * rj * invd[m] * invd[m + 1];
            val[m] = 0.0f;
        }

        float4* outp = (float4*)(out + OA + ((size_t)k << 16) + j0);
        for (int i = 0; i < 256; i++) {
            float tv = t_sh[grp][i];
            float4 v;
            #pragma unroll
            for (int m = 0; m < 4; m++) {
                int j = j0 + m;
                val[m] = (i == j + 1) ? start[m] : val[m] * tv;
                float vv = (i < j) ? 0.0f : ((i == j) ? diag[m] : val[m]);
                ((float*)&v)[m] = vv;
            }
            outp[(size_t)i << 6] = v;
        }
    } else {
        // ========== GBT_B: thread per timestep, float4-batched stores =====
        __shared__ float rsh[256];
        rsh[tid] = __ldg(Bv + tid);
        __syncthreads();
        const int k = ((bid - 257) << 8) + tid;
        const float s = frcp((float)(k + 1));
        const float h = 0.5f * s;
        float S = 0.0f;
        float4* outB = (float4*)(out + OB + ((size_t)k << 8));
        const float4* r4p = (const float4*)rsh;
        #pragma unroll 4
        for (int i4 = 0; i4 < 64; i4++) {
            float4 r4 = r4p[i4];
            float4 v;
            #pragma unroll
            for (int m = 0; m < 4; m++) {
                int i = (i4 << 2) + m;
                float r    = (&r4.x)[m];
                float invd = frcp(fmaf(h, (float)(i + 1), 1.0f));
                float x    = r * fmaf(-h, S, 1.0f) * invd;
                (&v.x)[m]  = s * x;
                S = fmaf(r, x, S);
            }
            outB[i4] = v;
        }
    }
}

extern "C" void kernel_launch(void* const* d_in, const int* in_sizes, int n_in,
                              void* d_out, int out_size) {
    const float* f          = (const float*)d_in[0];
    const float* init_state = (const float*)d_in[1];
    const float* Bv         = (const float*)d_in[3];
    cudaFuncSetAttribute(hippo_fused, cudaFuncAttributeMaxDynamicSharedMemorySize,
                         SMEMB);
    hippo_fused<<<261, 256, SMEMB>>>(f, init_state, Bv, (float*)d_out);
}